// round 4
// baseline (speedup 1.0000x reference)
#include <cuda_runtime.h>
#include <math.h>

#define NBLK 5
#define NSEG 4
#define BB   32
#define LL   128
#define NP   1024
#define EE   768
#define HH   512
#define PP   256
#define HDD  128
#define GG   2048
#define MT   4096
#define SCALE 0.08838834764831845f

// ---- scratch arena: phase-disjoint regions, 240 MB total ----
// Phase A (MLP):        mid @ OFF_MID (aliases gih region, dead before gih written)
//                       h   @ OFF_H
// Phase B (LSTM):       gih @ 0 (reads h / h0seq, both outside [0,GIH))
//                       h0seq @ OFF_H0SEQ
// Phase C (attention):  K @ 0, V @ OFF_V (gih dead)
#define OFF_GIH   0L
#define OFF_MID   0L
#define OFF_H0SEQ 41943040L                 // 5*4096*2048
#define OFF_H     52428800L                 // + 5*4096*512
#define OFF_K     0L
#define OFF_V     16777216L                 // 32*1024*512
#define ARENA_FLOATS 62914560L              // 240 MB

__device__ __align__(16) float g_arena[ARENA_FLOATS];
__device__ __align__(16) float g_hbuf [2*NBLK*BB*HH];
__device__ __align__(16) float g_cbuf [NBLK*BB*HH];
__device__ __align__(16) float g_gb   [NBLK*2*GG];
__device__ __align__(16) float g_last [NBLK*BB*HH];
__device__ __align__(16) float g_blk  [NBLK*BB*HH];
__device__ __align__(16) float g_q    [NSEG*BB*HH];
__device__ __align__(16) float g_att  [NSEG*BB*HH];
__device__ __align__(16) float g_res  [NSEG*BB*HH];
__device__ int   g_anyv [NSEG*BB];
__device__ __align__(16) float g_c1   [BB*128];
__device__ __align__(16) float g_c2   [BB*16];
__device__ __align__(16) float g_c3   [BB*3];

// ---- generic tiled GEMM: C = act(A@W + bias), batched over blockIdx.z ----
template<int ACT>  // 0 none, 1 leaky relu, 2 relu
__global__ void gemm_k(const float* __restrict__ A0, long sA,
                       const float* __restrict__ W0, long sW,
                       const float* __restrict__ b0, long sB,
                       float* __restrict__ C0, long sC,
                       int M, int K, int N)
{
    const float* A = A0 + (long)blockIdx.z * sA;
    const float* W = W0 + (long)blockIdx.z * sW;
    const float* bias = b0 + (long)blockIdx.z * sB;
    float* C = C0 + (long)blockIdx.z * sC;
    int bm = blockIdx.y * 64, bn = blockIdx.x * 64, tid = threadIdx.x;

    __shared__ __align__(16) float shA[16][68];
    __shared__ __align__(16) float shW[16][64];
    int tm = (tid >> 4) * 4, tn = (tid & 15) * 4;
    float acc[4][4] = {};

    for (int k0 = 0; k0 < K; k0 += 16) {
        #pragma unroll
        for (int i = 0; i < 4; i++) {
            int e = tid + i * 256, m = e >> 4, kk = e & 15;
            int gm = bm + m;
            shA[kk][m] = (gm < M) ? A[(long)gm * K + k0 + kk] : 0.f;
        }
        #pragma unroll
        for (int i = 0; i < 4; i++) {
            int e = tid + i * 256, kk = e >> 6, n = e & 63;
            int gn = bn + n;
            shW[kk][n] = (gn < N) ? W[(long)(k0 + kk) * N + gn] : 0.f;
        }
        __syncthreads();
        #pragma unroll
        for (int kk = 0; kk < 16; kk++) {
            float4 av = *(const float4*)&shA[kk][tm];
            float4 bv = *(const float4*)&shW[kk][tn];
            float a[4] = {av.x, av.y, av.z, av.w};
            float b[4] = {bv.x, bv.y, bv.z, bv.w};
            #pragma unroll
            for (int i = 0; i < 4; i++)
                #pragma unroll
                for (int j = 0; j < 4; j++)
                    acc[i][j] += a[i] * b[j];
        }
        __syncthreads();
    }
    #pragma unroll
    for (int i = 0; i < 4; i++) {
        int m = bm + tm + i;
        if (m >= M) continue;
        #pragma unroll
        for (int j = 0; j < 4; j++) {
            int n = bn + tn + j;
            if (n >= N) continue;
            float v = acc[i][j] + bias[n];
            if (ACT == 1) v = v > 0.f ? v : 0.01f * v;
            if (ACT == 2) v = fmaxf(v, 0.f);
            C[(long)m * N + n] = v;
        }
    }
}

__global__ void zero_k(float* p, int n) {
    int i = blockIdx.x * 256 + threadIdx.x;
    if (i < n) p[i] = 0.f;
}
__global__ void gb_k(const float* __restrict__ bih, const float* __restrict__ bhh) {
    int i = blockIdx.x * 256 + threadIdx.x;
    if (i < NBLK * 2 * GG) g_gb[i] = bih[i] + bhh[i];
}

// ---- fused LSTM step: grid (64 unit-tiles, 5 blk, 2 m-halves), 128 thr ----
__global__ void lstm_step_k(const float* __restrict__ Whh_all,
                            const float* __restrict__ hread,
                            float* __restrict__ hwrite,
                            const int* __restrict__ tlen,
                            int layer, int t)
{
    int blk = blockIdx.y, h0 = blockIdx.x * 8, ms = blockIdx.z * 16;
    int tid = threadIdx.x;
    const float* A = hread + ((long)blk * BB + ms) * HH;
    const float* W = Whh_all + (long)(blk * 2 + layer) * HH * GG;
    const float* G = g_arena + OFF_GIH + ((long)blk * MT + t) * GG;

    __shared__ __align__(16) float shH[16][17];
    __shared__ __align__(16) float shW[16][32];
    __shared__ float sg[16][36];

    int tm = tid >> 3, tn = (tid & 7) * 4;
    float acc[4] = {0.f, 0.f, 0.f, 0.f};

    for (int k0 = 0; k0 < HH; k0 += 16) {
        #pragma unroll
        for (int i = 0; i < 2; i++) {
            int e = tid + i * 128, m = e >> 4, kk = e & 15;
            shH[kk][m] = A[(long)m * HH + k0 + kk];
        }
        #pragma unroll
        for (int i = 0; i < 4; i++) {
            int e = tid + i * 128, kk = e >> 5, n = e & 31;
            int col = (n >> 3) * HH + h0 + (n & 7);
            shW[kk][n] = W[(long)(k0 + kk) * GG + col];
        }
        __syncthreads();
        #pragma unroll
        for (int kk = 0; kk < 16; kk++) {
            float a = shH[kk][tm];
            float4 bv = *(const float4*)&shW[kk][tn];
            acc[0] += a * bv.x; acc[1] += a * bv.y;
            acc[2] += a * bv.z; acc[3] += a * bv.w;
        }
        __syncthreads();
    }
    {
        int mg = ms + tm;
        long grow = (long)mg * LL * GG;
        #pragma unroll
        for (int j = 0; j < 4; j++) {
            int n = tn + j;
            int col = (n >> 3) * HH + h0 + (n & 7);
            sg[tm][n] = acc[j] + G[grow + col];
        }
    }
    __syncthreads();
    {
        int m = tid >> 3, u = tid & 7, mg = ms + m;
        float gi = sg[m][u], gf = sg[m][8 + u], gg2 = sg[m][16 + u], go = sg[m][24 + u];
        float ii = 1.f / (1.f + expf(-gi));
        float ff = 1.f / (1.f + expf(-gf));
        float gv = tanhf(gg2);
        float oo = 1.f / (1.f + expf(-go));
        long sidx = ((long)blk * BB + mg) * HH + h0 + u;
        float c = ff * g_cbuf[sidx] + ii * gv;
        float h = oo * tanhf(c);
        g_cbuf[sidx] = c;
        hwrite[sidx] = h;
        if (layer == 0)
            g_arena[OFF_H0SEQ + ((long)blk * MT + (long)mg * LL + t) * HH + h0 + u] = h;
        else if (t == tlen[mg * NBLK + blk] - 1)
            g_last[sidx] = h;
    }
}

__global__ void any_k(const int* __restrict__ mask) {
    int s = blockIdx.x, b = blockIdx.y, v = 0;
    for (int n = threadIdx.x; n < NP; n += 256)
        v |= (mask[b * NP + n] == s + 1);
    v = __syncthreads_or(v);
    if (threadIdx.x == 0) g_anyv[s * BB + b] = v;
}

// ---- attention per (head, b) for segment s; K/V live in arena ----
__global__ void attn_k(const int* __restrict__ mask, int s)
{
    int h = blockIdx.x, b = blockIdx.y, tid = threadIdx.x;
    __shared__ __align__(16) float sq[128];
    __shared__ float sc[NP];
    __shared__ float red[128];

    sq[tid] = g_q[((long)s * BB + b) * HH + h * HDD + tid];
    __syncthreads();

    const float* kb = g_arena + OFF_K + (long)b * NP * HH + h * HDD;
    const float4* sq4 = (const float4*)sq;
    #pragma unroll
    for (int j = 0; j < 8; j++) {
        int n = tid + j * 128;
        const float4* kr4 = (const float4*)(kb + (long)n * HH);
        float acc = 0.f;
        #pragma unroll
        for (int d4 = 0; d4 < 32; d4++) {
            float4 kv = kr4[d4], qv = sq4[d4];
            acc += kv.x * qv.x + kv.y * qv.y + kv.z * qv.z + kv.w * qv.w;
        }
        sc[n] = (mask[b * NP + n] == s + 1) ? acc * SCALE : -1e9f;
    }
    __syncthreads();

    float lm = -3.4e38f;
    #pragma unroll
    for (int j = 0; j < 8; j++) lm = fmaxf(lm, sc[tid + j * 128]);
    red[tid] = lm; __syncthreads();
    for (int w = 64; w > 0; w >>= 1) {
        if (tid < w) red[tid] = fmaxf(red[tid], red[tid + w]);
        __syncthreads();
    }
    float mx = red[0];
    __syncthreads();
    float ls = 0.f;
    #pragma unroll
    for (int j = 0; j < 8; j++) {
        int n = tid + j * 128;
        float e = expf(sc[n] - mx);
        sc[n] = e; ls += e;
    }
    __syncthreads();
    red[tid] = ls; __syncthreads();
    for (int w = 64; w > 0; w >>= 1) {
        if (tid < w) red[tid] += red[tid + w];
        __syncthreads();
    }
    float inv = 1.f / red[0];

    const float* vb = g_arena + OFF_V + (long)b * NP * HH + h * HDD + tid;
    float o0 = 0.f, o1 = 0.f, o2 = 0.f, o3 = 0.f;
    for (int n = 0; n < NP; n += 4) {
        o0 += sc[n]     * vb[(long)n * HH];
        o1 += sc[n + 1] * vb[(long)(n + 1) * HH];
        o2 += sc[n + 2] * vb[(long)(n + 2) * HH];
        o3 += sc[n + 3] * vb[(long)(n + 3) * HH];
    }
    g_att[((long)s * BB + b) * HH + h * HDD + tid] = (o0 + o1 + o2 + o3) * inv;
}

// ---- final assembly: tg | segs(+res where any) | class_pred | cls_feat ----
__global__ void assemble_k(float* __restrict__ out, int total)
{
    int i = blockIdx.x * 256 + threadIdx.x;
    if (i >= total) return;
    const int TG = BB * HH;
    if (i < TG) { out[i] = g_blk[i]; return; }
    if (i < 5 * TG) {
        int j = i - TG, s = j >> 14, r = j & 16383, b = r >> 9;
        float v = g_blk[(s + 1) * TG + r];
        if (g_anyv[s * BB + b]) v += g_res[s * TG + r];
        out[i] = v; return;
    }
    if (i < 5 * TG + BB * 3) { out[i] = g_c3[i - 5 * TG]; return; }
    out[i] = g_blk[i - (5 * TG + BB * 3)];
}

extern "C" void kernel_launch(void* const* d_in, const int* in_sizes, int n_in,
                              void* d_out, int out_size)
{
    (void)in_sizes; (void)n_in; (void)out_size;
    const int*   tlen = (const int*)d_in[5];
    const float* radar= (const float*)d_in[6];
    const int*   mask = (const int*)d_in[7];
    const float* W1   = (const float*)d_in[8];
    const float* b1   = (const float*)d_in[9];
    const float* W2   = (const float*)d_in[10];
    const float* b2   = (const float*)d_in[11];
    const float* Wih  = (const float*)d_in[12];
    const float* Whh  = (const float*)d_in[13];
    const float* bih  = (const float*)d_in[14];
    const float* bhh  = (const float*)d_in[15];
    const float* linW = (const float*)d_in[16];
    const float* linb = (const float*)d_in[17];
    const float* Wq   = (const float*)d_in[18];
    const float* bq   = (const float*)d_in[19];
    const float* Wk   = (const float*)d_in[20];
    const float* bk   = (const float*)d_in[21];
    const float* Wv   = (const float*)d_in[22];
    const float* bv   = (const float*)d_in[23];
    const float* Wo   = (const float*)d_in[24];
    const float* bo   = (const float*)d_in[25];
    const float* cW1  = (const float*)d_in[26];
    const float* cb1  = (const float*)d_in[27];
    const float* cW2  = (const float*)d_in[28];
    const float* cb2  = (const float*)d_in[29];
    const float* cW3  = (const float*)d_in[30];
    const float* cb3  = (const float*)d_in[31];

    float *p_arena, *p_hbuf, *p_cbuf, *p_gb, *p_last, *p_blk;
    float *p_q, *p_att, *p_res, *p_c1, *p_c2, *p_c3;
    cudaGetSymbolAddress((void**)&p_arena, g_arena);
    cudaGetSymbolAddress((void**)&p_hbuf, g_hbuf);
    cudaGetSymbolAddress((void**)&p_cbuf, g_cbuf);
    cudaGetSymbolAddress((void**)&p_gb,   g_gb);
    cudaGetSymbolAddress((void**)&p_last, g_last);
    cudaGetSymbolAddress((void**)&p_blk,  g_blk);
    cudaGetSymbolAddress((void**)&p_q,    g_q);
    cudaGetSymbolAddress((void**)&p_att,  g_att);
    cudaGetSymbolAddress((void**)&p_res,  g_res);
    cudaGetSymbolAddress((void**)&p_c1,   g_c1);
    cudaGetSymbolAddress((void**)&p_c2,   g_c2);
    cudaGetSymbolAddress((void**)&p_c3,   g_c3);

    float* p_mid   = p_arena + OFF_MID;
    float* p_h     = p_arena + OFF_H;
    float* p_gih   = p_arena + OFF_GIH;
    float* p_h0seq = p_arena + OFF_H0SEQ;
    float* p_kbuf  = p_arena + OFF_K;
    float* p_vbuf  = p_arena + OFF_V;

    const long SHC = (long)NBLK * BB * HH;   // h/c state elems per buffer

    gb_k<<<(NBLK * 2 * GG + 255) / 256, 256>>>(bih, bhh);

    // per-text-block MLP (5 separate launches since texts are separate inputs)
    for (int i = 0; i < 5; i++) {
        const float* ti = (const float*)d_in[i];
        gemm_k<1><<<dim3(8, 64, 1), 256>>>(ti, 0, W1 + (long)i * EE * HH, 0,
                                           b1 + (long)i * HH, 0,
                                           p_mid + (long)i * MT * HH, 0, MT, EE, HH);
    }
    gemm_k<0><<<dim3(8, 64, NBLK), 256>>>(p_mid, (long)MT * HH, W2, (long)HH * HH,
                                          b2, HH, p_h, (long)MT * HH, MT, HH, HH);

    for (int layer = 0; layer < 2; layer++) {
        const float* X = (layer == 0) ? p_h : p_h0seq;
        gemm_k<0><<<dim3(32, 64, NBLK), 256>>>(X, (long)MT * HH,
                                               Wih + (long)layer * HH * GG, 2L * HH * GG,
                                               p_gb + (long)layer * GG, 2L * GG,
                                               p_gih, (long)MT * GG, MT, HH, GG);
        zero_k<<<(int)((2 * SHC + 255) / 256), 256>>>(p_hbuf, (int)(2 * SHC));
        zero_k<<<(int)((SHC + 255) / 256), 256>>>(p_cbuf, (int)SHC);
        for (int t = 0; t < LL; t++) {
            const float* hr = p_hbuf + (t & 1) * SHC;
            float* hw = p_hbuf + ((t + 1) & 1) * SHC;
            lstm_step_k<<<dim3(64, NBLK, 2), 128>>>(Whh, hr, hw, tlen, layer, t);
        }
    }

    gemm_k<0><<<dim3(8, 1, NBLK), 256>>>(p_last, (long)BB * HH, linW, (long)HH * HH,
                                         linb, HH, p_blk, (long)BB * HH, BB, HH, HH);

    // q projections for all 4 segments
    gemm_k<0><<<dim3(8, 1, NSEG), 256>>>(p_blk + (long)BB * HH, (long)BB * HH,
                                         Wq, (long)HH * HH, bq, HH,
                                         p_q, (long)BB * HH, BB, HH, HH);
    any_k<<<dim3(NSEG, BB), 256>>>(mask);

    // per-seg K/V projection + attention (K/V buffers reused each seg)
    for (int s = 0; s < NSEG; s++) {
        gemm_k<0><<<dim3(8, 512, 1), 256>>>(radar, 0, Wk + (long)s * PP * HH, 0,
                                            bk + (long)s * HH, 0,
                                            p_kbuf, 0, BB * NP, PP, HH);
        gemm_k<0><<<dim3(8, 512, 1), 256>>>(radar, 0, Wv + (long)s * PP * HH, 0,
                                            bv + (long)s * HH, 0,
                                            p_vbuf, 0, BB * NP, PP, HH);
        attn_k<<<dim3(4, BB), 128>>>(mask, s);
    }

    gemm_k<0><<<dim3(8, 1, NSEG), 256>>>(p_att, (long)BB * HH, Wo, (long)HH * HH,
                                         bo, HH, p_res, (long)BB * HH, BB, HH, HH);

    gemm_k<2><<<dim3(2, 1, 1), 256>>>(p_blk, 0, cW1, 0, cb1, 0, p_c1, 0, BB, HH, 128);
    gemm_k<2><<<dim3(1, 1, 1), 256>>>(p_c1, 0, cW2, 0, cb2, 0, p_c2, 0, BB, 128, 16);
    gemm_k<0><<<dim3(1, 1, 1), 256>>>(p_c2, 0, cW3, 0, cb3, 0, p_c3, 0, BB, 16, 3);

    const int TOTAL = BB * HH * 6 + BB * 3;   // 98400
    assemble_k<<<(TOTAL + 255) / 256, 256>>>((float*)d_out, TOTAL);
}